// round 13
// baseline (speedup 1.0000x reference)
#include <cuda_runtime.h>
#include <math.h>

#define B_  512
#define T_  512
#define H_  100
#define DI_ 101
#define DO_ 2

#define SCAN_CTAS 256
#define XP_CTAS   336
#define NTILES    8192          // 512 chains x 16 t-blocks of 32 steps
#define INS_STRIDE 36
#define SMEM_FLOATS (DI_ * H_ + DI_ * INS_STRIDE)   // 13736 floats = 54944 B

typedef unsigned long long ull;

__device__ float g_xp[(size_t)B_ * T_ * H_];   // 0.1*(inp@Wx^T + b)
__device__ int   g_flags[B_ * 16];             // [chain][tb] tile-produced flags

__device__ __forceinline__ ull fma2(ull a, ull b, ull c) {
    ull d;
    asm("fma.rn.f32x2 %0, %1, %2, %3;" : "=l"(d) : "l"(a), "l"(b), "l"(c));
    return d;
}
__device__ __forceinline__ ull add2(ull a, ull b) {
    ull d;
    asm("add.rn.f32x2 %0, %1, %2;" : "=l"(d) : "l"(a), "l"(b));
    return d;
}
__device__ __forceinline__ ull dup2(float a) {
    ull d;
    asm("mov.b64 %0, {%1, %1};" : "=l"(d) : "f"(a));
    return d;
}
__device__ __forceinline__ float2 u2f(ull v) {
    float2 f;
    asm("mov.b64 {%0, %1}, %2;" : "=f"(f.x), "=f"(f.y) : "l"(v));
    return f;
}
__device__ __forceinline__ void cp_async4(unsigned smem_addr, const void* gptr) {
    asm volatile("cp.async.ca.shared.global [%0], [%1], 4;"
                 :: "r"(smem_addr), "l"(gptr));
}

// ---------------------------------------------------------------------------
// Fused kernel: 592 CTAs x 128 threads, occ 4 (592 = 148*4, all co-resident).
//   CTAs [0, 256):   scan consumers, 2 chains each.
//   CTAs [256, 592): xp producers, grid-stride over 8192 32-row tiles in
//                    t-block-major order; publish g_flags[c*16+tb].
// Producers never wait -> forward progress guaranteed; only scan CTAs spin,
// and they are the first 256 CTAs (always resident).
// ---------------------------------------------------------------------------
__global__ void __launch_bounds__(128, 4) fused_kernel(
    const float* __restrict__ inp,    // [B*T, DI]
    const float* __restrict__ Wx,     // [H, DI]
    const float* __restrict__ bias,   // [H]
    const float* __restrict__ noise,  // [B, T, H]
    const float* __restrict__ Wh,     // [H, H]
    const float* __restrict__ ah0,    // [H]
    float* __restrict__ hstore)       // [B, T, H]
{
    extern __shared__ __align__(16) float smem[];
    const int tid = threadIdx.x;
    const int bx  = blockIdx.x;

    if (bx >= SCAN_CTAS) {
        // ================= XP producer =================
        float* Wx_s = smem;                 // [i][j] transposed, 0.1-prescaled
        float* in_s = smem + DI_ * H_;      // [i][r], stride 36

        const int tx = tid & 31;            // col quad (active tx < 25)
        const int ty = tid >> 5;            // warp 0..3 -> rows 8*ty..8*ty+7

        for (int idx = tid; idx < DI_ * H_; idx += 128) {
            int j = idx / DI_;
            int i = idx - j * DI_;
            Wx_s[i * H_ + j] = 0.1f * Wx[idx];
        }
        float bv[4] = {0.f, 0.f, 0.f, 0.f};
        if (tx < 25) {
#pragma unroll
            for (int c = 0; c < 4; c++) bv[c] = 0.1f * bias[4 * tx + c];
        }

        for (int n = bx - SCAN_CTAS; n < NTILES; n += XP_CTAS) {
            const int tb = n >> 9;          // t-block 0..15 (t-block-major!)
            const int c  = n & 511;         // chain
            const int rbase = c * T_ + tb * 32;

            __syncthreads();
            for (int idx = tid; idx < 32 * DI_; idx += 128) {
                int r = idx / DI_;
                int i = idx - r * DI_;
                in_s[i * INS_STRIDE + r] = inp[(size_t)(rbase + r) * DI_ + i];
            }
            __syncthreads();

            if (tx < 25) {
                ull acc[4][4];
#pragma unroll
                for (int p = 0; p < 4; p++)
#pragma unroll
                    for (int cc = 0; cc < 4; cc++) acc[p][cc] = dup2(bv[cc]);

#pragma unroll 4
                for (int i = 0; i < DI_; i++) {
                    ulonglong2 ap0 = *(const ulonglong2*)(in_s + i * INS_STRIDE + 8 * ty);
                    ulonglong2 ap1 = *(const ulonglong2*)(in_s + i * INS_STRIDE + 8 * ty + 4);
                    float4 wv = *(const float4*)(Wx_s + i * H_ + 4 * tx);
                    ull w0 = dup2(wv.x), w1 = dup2(wv.y), w2 = dup2(wv.z), w3 = dup2(wv.w);
                    acc[0][0] = fma2(ap0.x, w0, acc[0][0]);
                    acc[0][1] = fma2(ap0.x, w1, acc[0][1]);
                    acc[0][2] = fma2(ap0.x, w2, acc[0][2]);
                    acc[0][3] = fma2(ap0.x, w3, acc[0][3]);
                    acc[1][0] = fma2(ap0.y, w0, acc[1][0]);
                    acc[1][1] = fma2(ap0.y, w1, acc[1][1]);
                    acc[1][2] = fma2(ap0.y, w2, acc[1][2]);
                    acc[1][3] = fma2(ap0.y, w3, acc[1][3]);
                    acc[2][0] = fma2(ap1.x, w0, acc[2][0]);
                    acc[2][1] = fma2(ap1.x, w1, acc[2][1]);
                    acc[2][2] = fma2(ap1.x, w2, acc[2][2]);
                    acc[2][3] = fma2(ap1.x, w3, acc[2][3]);
                    acc[3][0] = fma2(ap1.y, w0, acc[3][0]);
                    acc[3][1] = fma2(ap1.y, w1, acc[3][1]);
                    acc[3][2] = fma2(ap1.y, w2, acc[3][2]);
                    acc[3][3] = fma2(ap1.y, w3, acc[3][3]);
                }
#pragma unroll
                for (int p = 0; p < 4; p++) {
                    float2 c0v = u2f(acc[p][0]);
                    float2 c1v = u2f(acc[p][1]);
                    float2 c2v = u2f(acc[p][2]);
                    float2 c3v = u2f(acc[p][3]);
                    int re = rbase + 8 * ty + 2 * p;
                    float4 oe; oe.x = c0v.x; oe.y = c1v.x; oe.z = c2v.x; oe.w = c3v.x;
                    float4 oo; oo.x = c0v.y; oo.y = c1v.y; oo.z = c2v.y; oo.w = c3v.y;
                    *(float4*)(g_xp + (size_t)re * H_ + 4 * tx)       = oe;
                    *(float4*)(g_xp + (size_t)(re + 1) * H_ + 4 * tx) = oo;
                }
            }
            __threadfence();
            __syncthreads();                 // all threads' STGs fenced
            if (tid == 0) atomicExch(&g_flags[c * 16 + tb], 1);
        }
        return;
    }

    // ================= SCAN consumer (2 chains) =================
    // smem: hsA [2][104] @0, hsB [2][104] @208, rxp [4][2][112] @416,
    //       rnz [4][2][112] @1312   (floats)
    float* hsA = smem;
    float* hsB = smem + 208;
    float* rxp = smem + 416;
    float* rnz = smem + 1312;

    const int lane = tid & 31;
    const int w    = tid >> 5;
    const int j    = 25 * w + lane;
    const bool act = lane < 25;
    const int c0   = bx * 2;
    const size_t CH = (size_t)T_ * H_;

    // 0.1*W_h row j as 50 packed k-pair regs
    ull wk[50];
    if (act) {
        const float2* wr = (const float2*)(Wh + j * H_);
#pragma unroll
        for (int kk = 0; kk < 50; kk++) {
            float2 v = wr[kk];
            float2 s; s.x = 0.1f * v.x; s.y = 0.1f * v.y;
            wk[kk] = *(ull*)&s;
        }
    }

    float ahA = 0.f, ahB = 0.f;
    if (act) {
        float a0 = ah0[j];
        ahA = a0; ahB = a0;
        float h0 = tanhf(fmaxf(a0, 0.f));
        hsA[j] = h0;           // buf 0
        hsB[j] = h0;
    }

    const float* xpA = g_xp   + (size_t)c0 * CH + j;
    const float* nzA = noise  + (size_t)c0 * CH + j;
    float*       htA = hstore + (size_t)c0 * CH + j;

    unsigned rxp_a = (unsigned)__cvta_generic_to_shared(rxp);
    unsigned rnz_a = (unsigned)__cvta_generic_to_shared(rnz);

    // ---- wait for both chains' t-block 0, then prefetch slots 0..2 ----
    if (tid < 2) {
        volatile int* f = &g_flags[(c0 + tid) * 16];
        while (*f == 0) __nanosleep(200);
    }
    __threadfence();
    __syncthreads();

#pragma unroll
    for (int p = 0; p < 3; p++) {
        if (act) {
            unsigned so = 4u * (p * 224 + j);
            cp_async4(rxp_a + so,            xpA + (size_t)p * H_);
            cp_async4(rxp_a + so + 4u * 112, xpA + CH + (size_t)p * H_);
            cp_async4(rnz_a + so,            nzA + (size_t)p * H_);
            cp_async4(rnz_a + so + 4u * 112, nzA + CH + (size_t)p * H_);
        }
        asm volatile("cp.async.commit_group;");
    }
    __syncthreads();

    int buf = 0;
    for (int t = 0; t < T_; t++) {
        const int tn = t + 3;
        // poll the producer flags once per 32 steps, before prefetching
        if (tn < T_ && (tn & 31) == 0) {
            if (tid < 2) {
                volatile int* f = &g_flags[(c0 + tid) * 16 + (tn >> 5)];
                while (*f == 0) __nanosleep(200);
            }
            __threadfence();
            __syncthreads();
        }
        if (act && tn < T_) {
            unsigned so = 4u * ((tn & 3) * 224 + j);
            cp_async4(rxp_a + so,            xpA + (size_t)tn * H_);
            cp_async4(rxp_a + so + 4u * 112, xpA + CH + (size_t)tn * H_);
            cp_async4(rnz_a + so,            nzA + (size_t)tn * H_);
            cp_async4(rnz_a + so + 4u * 112, nzA + CH + (size_t)tn * H_);
        }
        asm volatile("cp.async.commit_group;");
        asm volatile("cp.async.wait_group 3;");   // slot t complete

        if (act) {
            const ulonglong2* hpA = (const ulonglong2*)(hsA + buf * 104);
            const ulonglong2* hpB = (const ulonglong2*)(hsB + buf * 104);
            ull aA = 0, bA = 0, aB = 0, bB = 0;
#pragma unroll
            for (int kk = 0; kk < 25; kk++) {
                ulonglong2 vA = hpA[kk];
                ulonglong2 vB = hpB[kk];
                aA = fma2(vA.x, wk[2 * kk],     aA);
                bA = fma2(vA.y, wk[2 * kk + 1], bA);
                aB = fma2(vB.x, wk[2 * kk],     aB);
                bB = fma2(vB.y, wk[2 * kk + 1], bB);
            }
            float2 sA = u2f(add2(aA, bA));
            float2 sB = u2f(add2(aB, bB));
            float sumA = sA.x + sA.y;
            float sumB = sB.x + sB.y;

            const int s = t & 3;
            float xvA = rxp[s * 224 + j];
            float xvB = rxp[s * 224 + 112 + j];
            float nvA = rnz[s * 224 + j];
            float nvB = rnz[s * 224 + 112 + j];

            ahA = fmaf(0.9f, ahA, sumA + xvA);
            ahB = fmaf(0.9f, ahB, sumB + xvB);
            float xA = fmaxf(ahA, 0.f);
            float xB = fmaxf(ahB, 0.f);
            float eA = __expf(-2.f * xA);
            float eB = __expf(-2.f * xB);
            float hA = __fdividef(1.f - eA, 1.f + eA) + nvA;
            float hB = __fdividef(1.f - eB, 1.f + eB) + nvB;

            hsA[(buf ^ 1) * 104 + j] = hA;
            hsB[(buf ^ 1) * 104 + j] = hB;
            htA[(size_t)t * H_]      = hA;
            htA[CH + (size_t)t * H_] = hB;
        }
        buf ^= 1;
        __syncthreads();
    }
}

// ---------------------------------------------------------------------------
// Kernel C: output[r][d] = sum_j hstore[r][j] * W_y[d][j]
// ---------------------------------------------------------------------------
__global__ void __launch_bounds__(256) outproj_kernel(
    const float* __restrict__ hst,   // [B*T, H]
    const float* __restrict__ Wy,    // [DO, H]
    float* __restrict__ out)         // [B*T, DO]
{
    __shared__ float wy_s[DO_ * H_];
    const int tid = threadIdx.x;
    for (int idx = tid; idx < DO_ * H_; idx += 256) wy_s[idx] = Wy[idx];
    __syncthreads();

    const int lane = tid & 31;
    const int w    = tid >> 5;
    const size_t row = (size_t)blockIdx.x * 8 + w;

    float a0 = 0.f, a1 = 0.f;
    for (int j = lane; j < H_; j += 32) {
        float h = hst[row * H_ + j];
        a0 = fmaf(h, wy_s[j],      a0);
        a1 = fmaf(h, wy_s[H_ + j], a1);
    }
#pragma unroll
    for (int off = 16; off > 0; off >>= 1) {
        a0 += __shfl_down_sync(0xffffffffu, a0, off);
        a1 += __shfl_down_sync(0xffffffffu, a1, off);
    }
    if (lane == 0) {
        out[row * DO_ + 0] = a0;
        out[row * DO_ + 1] = a1;
    }
}

// ---------------------------------------------------------------------------
extern "C" void kernel_launch(void* const* d_in, const int* in_sizes, int n_in,
                              void* d_out, int out_size)
{
    const float* inp   = (const float*)d_in[0];  // [B,T,DI]
    const float* noise = (const float*)d_in[1];  // [B,T,H]
    const float* Wx    = (const float*)d_in[2];  // [H,DI]
    const float* bias  = (const float*)d_in[3];  // [H]
    const float* Wh    = (const float*)d_in[4];  // [H,H]
    const float* Wy    = (const float*)d_in[5];  // [DO,H]
    const float* ah0   = (const float*)d_in[6];  // [H]

    float* out    = (float*)d_out;                  // [B,T,DO] first
    float* hstore = out + (size_t)B_ * T_ * DO_;    // [B,T,H] second

    const int fused_smem = SMEM_FLOATS * (int)sizeof(float);   // 54944 B
    static int attr_done = 0;
    if (!attr_done) {
        cudaFuncSetAttribute(fused_kernel,
                             cudaFuncAttributeMaxDynamicSharedMemorySize, fused_smem);
        cudaFuncSetAttribute(fused_kernel,
                             cudaFuncAttributePreferredSharedMemoryCarveout,
                             cudaSharedmemCarveoutMaxShared);
        attr_done = 1;
    }

    fused_kernel<<<SCAN_CTAS + XP_CTAS, 128, fused_smem>>>(
        inp, Wx, bias, noise, Wh, ah0, hstore);
    outproj_kernel<<<(B_ * T_) / 8, 256>>>(hstore, Wy, out);
}

// round 14
// speedup vs baseline: 1.2384x; 1.2384x over previous
#include <cuda_runtime.h>
#include <math.h>

#define B_  512
#define T_  512
#define H_  100
#define DI_ 101
#define DO_ 2

typedef unsigned long long ull;

__device__ float g_xp[(size_t)B_ * T_ * H_];   // holds 0.1*(inp@Wx^T + b)

__device__ __forceinline__ ull fma2(ull a, ull b, ull c) {
    ull d;
    asm("fma.rn.f32x2 %0, %1, %2, %3;" : "=l"(d) : "l"(a), "l"(b), "l"(c));
    return d;
}
__device__ __forceinline__ ull add2(ull a, ull b) {
    ull d;
    asm("add.rn.f32x2 %0, %1, %2;" : "=l"(d) : "l"(a), "l"(b));
    return d;
}
__device__ __forceinline__ ull dup2(float a) {
    ull d;
    asm("mov.b64 %0, {%1, %1};" : "=l"(d) : "f"(a));
    return d;
}
__device__ __forceinline__ ull pack2(float lo, float hi) {
    ull d;
    asm("mov.b64 %0, {%1, %2};" : "=l"(d) : "f"(lo), "f"(hi));
    return d;
}
__device__ __forceinline__ float2 u2f(ull v) {
    float2 f;
    asm("mov.b64 {%0, %1}, %2;" : "=f"(f.x), "=f"(f.y) : "l"(v));
    return f;
}
__device__ __forceinline__ void cp_async4(unsigned smem_addr, const void* gptr) {
    asm volatile("cp.async.ca.shared.global [%0], [%1], 4;"
                 :: "r"(smem_addr), "l"(gptr));
}

// ---------------------------------------------------------------------------
// Kernel A: g_xp[r][j] = 0.1*(sum_i input[r][i]*Wx[j][i] + b[j])
// EXACT round-7 kernel (measured 163.9us).
// ---------------------------------------------------------------------------
#define INS_STRIDE 68
__global__ void __launch_bounds__(256, 3) xp_gemm_kernel(
    const float* __restrict__ inp,   // [B*T, DI]
    const float* __restrict__ Wx,    // [H, DI]
    const float* __restrict__ bias)  // [H]
{
    extern __shared__ __align__(16) float smem[];
    float* Wx_s = smem;                 // [i][j]  (pre-scaled by 0.1)
    float* in_s = smem + DI_ * H_;      // [i][r]

    const int tid = threadIdx.x;
    const int tx  = tid & 31;   // col quad (active tx < 25)
    const int ty  = tid >> 5;   // warp id (0..7) -> rows 8*ty..8*ty+7

    for (int idx = tid; idx < DI_ * H_; idx += 256) {
        int j = idx / DI_;
        int i = idx - j * DI_;
        Wx_s[i * H_ + j] = 0.1f * Wx[idx];
    }

    float bv[4] = {0.f, 0.f, 0.f, 0.f};
    if (tx < 25) {
#pragma unroll
        for (int c = 0; c < 4; c++) bv[c] = 0.1f * bias[4 * tx + c];
    }

    const int ntiles = (B_ * T_) / 64;   // 4096
    for (int tile = blockIdx.x; tile < ntiles; tile += gridDim.x) {
        __syncthreads();
        const int rbase = tile * 64;
        for (int idx = tid; idx < 64 * DI_; idx += 256) {
            int r = idx / DI_;
            int i = idx - r * DI_;
            in_s[i * INS_STRIDE + r] = inp[(size_t)(rbase + r) * DI_ + i];
        }
        __syncthreads();

        if (tx < 25) {
            ull acc[4][4];
#pragma unroll
            for (int p = 0; p < 4; p++)
#pragma unroll
                for (int c = 0; c < 4; c++) acc[p][c] = dup2(bv[c]);

#pragma unroll 4
            for (int i = 0; i < DI_; i++) {
                ulonglong2 ap0 = *(const ulonglong2*)(in_s + i * INS_STRIDE + 8 * ty);
                ulonglong2 ap1 = *(const ulonglong2*)(in_s + i * INS_STRIDE + 8 * ty + 4);
                float4 wv = *(const float4*)(Wx_s + i * H_ + 4 * tx);
                ull w0 = dup2(wv.x), w1 = dup2(wv.y), w2 = dup2(wv.z), w3 = dup2(wv.w);
                acc[0][0] = fma2(ap0.x, w0, acc[0][0]);
                acc[0][1] = fma2(ap0.x, w1, acc[0][1]);
                acc[0][2] = fma2(ap0.x, w2, acc[0][2]);
                acc[0][3] = fma2(ap0.x, w3, acc[0][3]);
                acc[1][0] = fma2(ap0.y, w0, acc[1][0]);
                acc[1][1] = fma2(ap0.y, w1, acc[1][1]);
                acc[1][2] = fma2(ap0.y, w2, acc[1][2]);
                acc[1][3] = fma2(ap0.y, w3, acc[1][3]);
                acc[2][0] = fma2(ap1.x, w0, acc[2][0]);
                acc[2][1] = fma2(ap1.x, w1, acc[2][1]);
                acc[2][2] = fma2(ap1.x, w2, acc[2][2]);
                acc[2][3] = fma2(ap1.x, w3, acc[2][3]);
                acc[3][0] = fma2(ap1.y, w0, acc[3][0]);
                acc[3][1] = fma2(ap1.y, w1, acc[3][1]);
                acc[3][2] = fma2(ap1.y, w2, acc[3][2]);
                acc[3][3] = fma2(ap1.y, w3, acc[3][3]);
            }
#pragma unroll
            for (int p = 0; p < 4; p++) {
                float2 c0 = u2f(acc[p][0]);
                float2 c1 = u2f(acc[p][1]);
                float2 c2 = u2f(acc[p][2]);
                float2 c3 = u2f(acc[p][3]);
                int re = rbase + 8 * ty + 2 * p;
                float4 oe; oe.x = c0.x; oe.y = c1.x; oe.z = c2.x; oe.w = c3.x;
                float4 oo; oo.x = c0.y; oo.y = c1.y; oo.z = c2.y; oo.w = c3.y;
                *(float4*)(g_xp + (size_t)re * H_ + 4 * tx)       = oe;
                *(float4*)(g_xp + (size_t)(re + 1) * H_ + 4 * tx) = oo;
            }
        }
    }
}

// ---------------------------------------------------------------------------
// Kernel B: sequential scan — round-7 structure (512 CTAs x 128 threads,
// 1 chain/CTA, occ 4, cp.async ring, de-phase stagger) with ONE change:
// FOUR independent packed accumulators (dependency depth 25 -> 13).
// ---------------------------------------------------------------------------
__global__ void __launch_bounds__(128, 4) scan_kernel(
    const float* __restrict__ noise,   // [B, T, H]
    const float* __restrict__ Wh,      // [H, H]
    const float* __restrict__ ah0,     // [H]
    float* __restrict__ hstore)        // [B, T, H]
{
    __shared__ __align__(16) float hs[2][104];
    __shared__ __align__(16) float rxp[4][100];
    __shared__ __align__(16) float rnz[4][100];

    const int tid  = threadIdx.x;
    const int lane = tid & 31;
    const int w    = tid >> 5;
    const int j    = 25 * w + lane;
    const bool act = lane < 25;

    {
        long long lim = (long long)((blockIdx.x & 3) * 256);
        long long s0 = clock64();
        while (clock64() - s0 < lim) {}
    }

    ull wk[50];
    if (act) {
        const float2* wr = (const float2*)(Wh + j * H_);
#pragma unroll
        for (int kk = 0; kk < 50; kk++) {
            float2 v = wr[kk];
            float2 s; s.x = 0.1f * v.x; s.y = 0.1f * v.y;
            wk[kk] = *(ull*)&s;
        }
    }

    float ah = 0.f;
    if (act) {
        ah = ah0[j];
        hs[0][j] = tanhf(fmaxf(ah, 0.f));
    }

    const float* xp_src = g_xp  + (size_t)blockIdx.x * (T_ * H_) + j;
    const float* nz_src = noise + (size_t)blockIdx.x * (T_ * H_) + j;
    float* hst = hstore + (size_t)blockIdx.x * (T_ * H_) + j;

    unsigned rxp_a = (unsigned)__cvta_generic_to_shared(rxp);
    unsigned rnz_a = (unsigned)__cvta_generic_to_shared(rnz);

#pragma unroll
    for (int p = 0; p < 3; p++) {
        if (act) {
            cp_async4(rxp_a + 4u * (p * 100 + j), xp_src + (size_t)p * H_);
            cp_async4(rnz_a + 4u * (p * 100 + j), nz_src + (size_t)p * H_);
        }
        asm volatile("cp.async.commit_group;");
    }
    __syncthreads();

    int buf = 0;
    for (int t = 0; t < T_; t++) {
        if (act && t + 3 < T_) {
            int s = (t + 3) & 3;
            cp_async4(rxp_a + 4u * (s * 100 + j), xp_src + (size_t)(t + 3) * H_);
            cp_async4(rnz_a + 4u * (s * 100 + j), nz_src + (size_t)(t + 3) * H_);
        }
        asm volatile("cp.async.commit_group;");
        asm volatile("cp.async.wait_group 3;");

        if (act) {
            float xpv = rxp[t & 3][j];
            float nzv = rnz[t & 3][j];

            const ulonglong2* h4 = (const ulonglong2*)hs[buf];
            ull a = 0, b = 0, c = 0, d = 0;   // 4 independent chains, depth 13
#pragma unroll
            for (int kk = 0; kk < 25; kk++) {
                ulonglong2 v = h4[kk];
                if (kk & 1) {
                    c = fma2(v.x, wk[2 * kk],     c);
                    d = fma2(v.y, wk[2 * kk + 1], d);
                } else {
                    a = fma2(v.x, wk[2 * kk],     a);
                    b = fma2(v.y, wk[2 * kk + 1], b);
                }
            }
            float2 s = u2f(add2(add2(a, b), add2(c, d)));
            float sum = s.x + s.y;

            ah = fmaf(0.9f, ah, sum + xpv);
            float x = fmaxf(ah, 0.f);
            float e = __expf(-2.f * x);
            float h = __fdividef(1.f - e, 1.f + e) + nzv;
            hs[buf ^ 1][j] = h;
            hst[(size_t)t * H_] = h;
        }
        buf ^= 1;
        __syncthreads();
    }
}

// ---------------------------------------------------------------------------
// Kernel C: outproj, THREAD-PER-ROW. 25x float4 LDG per row (high MLP),
// wy packed (wy0_j|wy1_j) b64 smem broadcasts, fma2, 8B coalesced store.
// ---------------------------------------------------------------------------
__global__ void __launch_bounds__(256) outproj_kernel(
    const float* __restrict__ hst,   // [B*T, H]
    const float* __restrict__ Wy,    // [DO, H]
    float* __restrict__ out)         // [B*T, DO]
{
    __shared__ ull wy2[H_];
    const int tid = threadIdx.x;
    if (tid < H_) wy2[tid] = pack2(Wy[tid], Wy[H_ + tid]);
    __syncthreads();

    const size_t row = (size_t)blockIdx.x * 256 + tid;
    const float4* rp = (const float4*)(hst + row * H_);   // 400B rows, 16B aligned

    ull acc0 = 0, acc1 = 0, acc2 = 0, acc3 = 0;
#pragma unroll
    for (int q = 0; q < 25; q++) {
        float4 v = rp[q];
        acc0 = fma2(dup2(v.x), wy2[4 * q + 0], acc0);
        acc1 = fma2(dup2(v.y), wy2[4 * q + 1], acc1);
        acc2 = fma2(dup2(v.z), wy2[4 * q + 2], acc2);
        acc3 = fma2(dup2(v.w), wy2[4 * q + 3], acc3);
    }
    ull r = add2(add2(acc0, acc1), add2(acc2, acc3));
    *(ull*)(out + row * DO_) = r;
}

// ---------------------------------------------------------------------------
extern "C" void kernel_launch(void* const* d_in, const int* in_sizes, int n_in,
                              void* d_out, int out_size)
{
    const float* inp   = (const float*)d_in[0];  // [B,T,DI]
    const float* noise = (const float*)d_in[1];  // [B,T,H]
    const float* Wx    = (const float*)d_in[2];  // [H,DI]
    const float* bias  = (const float*)d_in[3];  // [H]
    const float* Wh    = (const float*)d_in[4];  // [H,H]
    const float* Wy    = (const float*)d_in[5];  // [DO,H]
    const float* ah0   = (const float*)d_in[6];  // [H]

    float* out    = (float*)d_out;                  // [B,T,DO] first
    float* hstore = out + (size_t)B_ * T_ * DO_;    // [B,T,H] second

    const int xp_smem = (DI_ * H_ + DI_ * INS_STRIDE) * (int)sizeof(float);  // 67872 B
    static int attr_done = 0;
    if (!attr_done) {
        cudaFuncSetAttribute(xp_gemm_kernel,
                             cudaFuncAttributeMaxDynamicSharedMemorySize, xp_smem);
        cudaFuncSetAttribute(xp_gemm_kernel,
                             cudaFuncAttributePreferredSharedMemoryCarveout,
                             cudaSharedmemCarveoutMaxShared);
        attr_done = 1;
    }

    xp_gemm_kernel<<<1024, 256, xp_smem>>>(inp, Wx, bias);
    scan_kernel<<<B_, 128>>>(noise, Wh, ah0, hstore);
    outproj_kernel<<<(B_ * T_) / 256, 256>>>(hstore, Wy, out);
}

// round 15
// speedup vs baseline: 1.2438x; 1.0044x over previous
#include <cuda_runtime.h>
#include <math.h>

#define B_  512
#define T_  512
#define H_  100
#define DI_ 101
#define DO_ 2

typedef unsigned long long ull;

__device__ float g_xp[(size_t)B_ * T_ * H_];   // holds 0.1*(inp@Wx^T + b)

__device__ __forceinline__ ull fma2(ull a, ull b, ull c) {
    ull d;
    asm("fma.rn.f32x2 %0, %1, %2, %3;" : "=l"(d) : "l"(a), "l"(b), "l"(c));
    return d;
}
__device__ __forceinline__ ull add2(ull a, ull b) {
    ull d;
    asm("add.rn.f32x2 %0, %1, %2;" : "=l"(d) : "l"(a), "l"(b));
    return d;
}
__device__ __forceinline__ ull dup2(float a) {
    ull d;
    asm("mov.b64 %0, {%1, %1};" : "=l"(d) : "f"(a));
    return d;
}
__device__ __forceinline__ ull pack2(float lo, float hi) {
    ull d;
    asm("mov.b64 %0, {%1, %2};" : "=l"(d) : "f"(lo), "f"(hi));
    return d;
}
__device__ __forceinline__ float2 u2f(ull v) {
    float2 f;
    asm("mov.b64 {%0, %1}, %2;" : "=f"(f.x), "=f"(f.y) : "l"(v));
    return f;
}

// ---------------------------------------------------------------------------
// Kernel A: g_xp[r][j] = 0.1*(sum_i input[r][i]*Wx[j][i] + b[j])
// EXACT round-7 kernel (measured 163.9-165.2us).
// ---------------------------------------------------------------------------
#define INS_STRIDE 68
__global__ void __launch_bounds__(256, 3) xp_gemm_kernel(
    const float* __restrict__ inp,   // [B*T, DI]
    const float* __restrict__ Wx,    // [H, DI]
    const float* __restrict__ bias)  // [H]
{
    extern __shared__ __align__(16) float smem[];
    float* Wx_s = smem;                 // [i][j]  (pre-scaled by 0.1)
    float* in_s = smem + DI_ * H_;      // [i][r]

    const int tid = threadIdx.x;
    const int tx  = tid & 31;   // col quad (active tx < 25)
    const int ty  = tid >> 5;   // warp id (0..7) -> rows 8*ty..8*ty+7

    for (int idx = tid; idx < DI_ * H_; idx += 256) {
        int j = idx / DI_;
        int i = idx - j * DI_;
        Wx_s[i * H_ + j] = 0.1f * Wx[idx];
    }

    float bv[4] = {0.f, 0.f, 0.f, 0.f};
    if (tx < 25) {
#pragma unroll
        for (int c = 0; c < 4; c++) bv[c] = 0.1f * bias[4 * tx + c];
    }

    const int ntiles = (B_ * T_) / 64;   // 4096
    for (int tile = blockIdx.x; tile < ntiles; tile += gridDim.x) {
        __syncthreads();
        const int rbase = tile * 64;
        for (int idx = tid; idx < 64 * DI_; idx += 256) {
            int r = idx / DI_;
            int i = idx - r * DI_;
            in_s[i * INS_STRIDE + r] = inp[(size_t)(rbase + r) * DI_ + i];
        }
        __syncthreads();

        if (tx < 25) {
            ull acc[4][4];
#pragma unroll
            for (int p = 0; p < 4; p++)
#pragma unroll
                for (int c = 0; c < 4; c++) acc[p][c] = dup2(bv[c]);

#pragma unroll 4
            for (int i = 0; i < DI_; i++) {
                ulonglong2 ap0 = *(const ulonglong2*)(in_s + i * INS_STRIDE + 8 * ty);
                ulonglong2 ap1 = *(const ulonglong2*)(in_s + i * INS_STRIDE + 8 * ty + 4);
                float4 wv = *(const float4*)(Wx_s + i * H_ + 4 * tx);
                ull w0 = dup2(wv.x), w1 = dup2(wv.y), w2 = dup2(wv.z), w3 = dup2(wv.w);
                acc[0][0] = fma2(ap0.x, w0, acc[0][0]);
                acc[0][1] = fma2(ap0.x, w1, acc[0][1]);
                acc[0][2] = fma2(ap0.x, w2, acc[0][2]);
                acc[0][3] = fma2(ap0.x, w3, acc[0][3]);
                acc[1][0] = fma2(ap0.y, w0, acc[1][0]);
                acc[1][1] = fma2(ap0.y, w1, acc[1][1]);
                acc[1][2] = fma2(ap0.y, w2, acc[1][2]);
                acc[1][3] = fma2(ap0.y, w3, acc[1][3]);
                acc[2][0] = fma2(ap1.x, w0, acc[2][0]);
                acc[2][1] = fma2(ap1.x, w1, acc[2][1]);
                acc[2][2] = fma2(ap1.x, w2, acc[2][2]);
                acc[2][3] = fma2(ap1.x, w3, acc[2][3]);
                acc[3][0] = fma2(ap1.y, w0, acc[3][0]);
                acc[3][1] = fma2(ap1.y, w1, acc[3][1]);
                acc[3][2] = fma2(ap1.y, w2, acc[3][2]);
                acc[3][3] = fma2(ap1.y, w3, acc[3][3]);
            }
#pragma unroll
            for (int p = 0; p < 4; p++) {
                float2 c0 = u2f(acc[p][0]);
                float2 c1 = u2f(acc[p][1]);
                float2 c2 = u2f(acc[p][2]);
                float2 c3 = u2f(acc[p][3]);
                int re = rbase + 8 * ty + 2 * p;
                float4 oe; oe.x = c0.x; oe.y = c1.x; oe.z = c2.x; oe.w = c3.x;
                float4 oo; oo.x = c0.y; oo.y = c1.y; oo.z = c2.y; oo.w = c3.y;
                *(float4*)(g_xp + (size_t)re * H_ + 4 * tx)       = oe;
                *(float4*)(g_xp + (size_t)(re + 1) * H_ + 4 * tx) = oo;
            }
        }
    }
}

// ---------------------------------------------------------------------------
// Kernel B: sequential scan — 2 warps per chain, 2 rows per thread,
// independent 64-thread NAMED barriers. 256 CTAs x 128 threads, occ 2
// (reg cap 255; wk0+wk1 = 200 regs).
//   pair = tid>>6 -> chain blockIdx.x*2 + pair (warps {0,1} / {2,3})
//   lane < 25 active; rows j0 = 50*wp + lane, j1 = j0 + 25
//   h loads SHARED across the 2 rows -> 25 LDS + 100 fma2 per thread-step.
//   sync: bar.sync (pair+1), 64  -- chains fully decoupled.
//   xp/noise: register prefetch ring, depth 2.
// ---------------------------------------------------------------------------
__global__ void __launch_bounds__(128, 2) scan_kernel(
    const float* __restrict__ noise,   // [B, T, H]
    const float* __restrict__ Wh,      // [H, H]
    const float* __restrict__ ah0,     // [H]
    float* __restrict__ hstore)        // [B, T, H]
{
    __shared__ __align__(16) float hs[2][2][104];   // [pair][buf][k]

    const int tid  = threadIdx.x;
    const int lane = tid & 31;
    const int wp   = (tid >> 5) & 1;    // warp within pair
    const int pair = tid >> 6;          // 0 or 1
    const bool act = lane < 25;
    const int j0   = 50 * wp + lane;
    const int j1   = j0 + 25;
    const int chain = blockIdx.x * 2 + pair;
    const int barid = pair + 1;         // named barriers 1 and 2

    // de-phase co-resident CTAs a little
    {
        long long lim = (long long)((blockIdx.x & 1) * 300);
        long long s0 = clock64();
        while (clock64() - s0 < lim) {}
    }

    // 0.1*W rows j0, j1 packed over k (k-pairs)
    ull wk0[50], wk1[50];
    if (act) {
        const float2* w0 = (const float2*)(Wh + j0 * H_);
        const float2* w1 = (const float2*)(Wh + j1 * H_);
#pragma unroll
        for (int kk = 0; kk < 50; kk++) {
            float2 a = w0[kk];
            float2 b = w1[kk];
            wk0[kk] = pack2(0.1f * a.x, 0.1f * a.y);
            wk1[kk] = pack2(0.1f * b.x, 0.1f * b.y);
        }
    }

    float ahx = 0.f, ahy = 0.f;
    if (act) {
        ahx = ah0[j0];
        ahy = ah0[j1];
        hs[pair][0][j0] = tanhf(fmaxf(ahx, 0.f));
        hs[pair][0][j1] = tanhf(fmaxf(ahy, 0.f));
    }

    const size_t base = (size_t)chain * (T_ * H_);
    const float* xps = g_xp  + base + j0;    // row j1 = +25
    const float* nzs = noise + base + j0;
    float*       hst = hstore + base + j0;

    // depth-2 register prefetch ring
    float xc0 = 0.f, xc1 = 0.f, nc0 = 0.f, nc1 = 0.f;   // step t
    float xn0 = 0.f, xn1 = 0.f, nn0 = 0.f, nn1 = 0.f;   // step t+1
    if (act) {
        xc0 = xps[0];       xc1 = xps[25];
        nc0 = nzs[0];       nc1 = nzs[25];
        xn0 = xps[H_];      xn1 = xps[H_ + 25];
        nn0 = nzs[H_];      nn1 = nzs[H_ + 25];
    }
    __syncthreads();   // covers hs init for both pairs

    int buf = 0;
    for (int t = 0; t < T_; t++) {
        // prefetch t+2
        float p0 = 0.f, p1 = 0.f, q0 = 0.f, q1 = 0.f;
        if (act && t + 2 < T_) {
            size_t o = (size_t)(t + 2) * H_;
            p0 = xps[o];  p1 = xps[o + 25];
            q0 = nzs[o];  q1 = nzs[o + 25];
        }

        if (act) {
            const ulonglong2* h4 = (const ulonglong2*)hs[pair][buf];
            ull a0 = 0, b0 = 0, a1 = 0, b1 = 0;
#pragma unroll
            for (int kk = 0; kk < 25; kk++) {
                ulonglong2 v = h4[kk];            // k = 4kk .. 4kk+3
                a0 = fma2(v.x, wk0[2 * kk],     a0);
                b0 = fma2(v.y, wk0[2 * kk + 1], b0);
                a1 = fma2(v.x, wk1[2 * kk],     a1);
                b1 = fma2(v.y, wk1[2 * kk + 1], b1);
            }
            float2 s0 = u2f(add2(a0, b0));
            float2 s1 = u2f(add2(a1, b1));
            float sum0 = s0.x + s0.y;
            float sum1 = s1.x + s1.y;

            ahx = fmaf(0.9f, ahx, sum0 + xc0);
            ahy = fmaf(0.9f, ahy, sum1 + xc1);
            float x0 = fmaxf(ahx, 0.f);
            float x1 = fmaxf(ahy, 0.f);
            float e0 = __expf(-2.f * x0);
            float e1 = __expf(-2.f * x1);
            float h0 = __fdividef(1.f - e0, 1.f + e0) + nc0;
            float h1 = __fdividef(1.f - e1, 1.f + e1) + nc1;

            hs[pair][buf ^ 1][j0] = h0;
            hs[pair][buf ^ 1][j1] = h1;
            size_t o = (size_t)t * H_;
            hst[o]      = h0;
            hst[o + 25] = h1;
        }
        // rotate ring
        xc0 = xn0; xc1 = xn1; nc0 = nn0; nc1 = nn1;
        xn0 = p0;  xn1 = p1;  nn0 = q0;  nn1 = q1;
        buf ^= 1;
        asm volatile("bar.sync %0, %1;" :: "r"(barid), "r"(64) : "memory");
    }
}

// ---------------------------------------------------------------------------
// Kernel C: outproj, THREAD-PER-ROW (round-14 version).
// ---------------------------------------------------------------------------
__global__ void __launch_bounds__(256) outproj_kernel(
    const float* __restrict__ hst,   // [B*T, H]
    const float* __restrict__ Wy,    // [DO, H]
    float* __restrict__ out)         // [B*T, DO]
{
    __shared__ ull wy2[H_];
    const int tid = threadIdx.x;
    if (tid < H_) wy2[tid] = pack2(Wy[tid], Wy[H_ + tid]);
    __syncthreads();

    const size_t row = (size_t)blockIdx.x * 256 + tid;
    const float4* rp = (const float4*)(hst + row * H_);

    ull acc0 = 0, acc1 = 0, acc2 = 0, acc3 = 0;
#pragma unroll
    for (int q = 0; q < 25; q++) {
        float4 v = rp[q];
        acc0 = fma2(dup2(v.x), wy2[4 * q + 0], acc0);
        acc1 = fma2(dup2(v.y), wy2[4 * q + 1], acc1);
        acc2 = fma2(dup2(v.z), wy2[4 * q + 2], acc2);
        acc3 = fma2(dup2(v.w), wy2[4 * q + 3], acc3);
    }
    ull r = add2(add2(acc0, acc1), add2(acc2, acc3));
    *(ull*)(out + row * DO_) = r;
}

// ---------------------------------------------------------------------------
extern "C" void kernel_launch(void* const* d_in, const int* in_sizes, int n_in,
                              void* d_out, int out_size)
{
    const float* inp   = (const float*)d_in[0];  // [B,T,DI]
    const float* noise = (const float*)d_in[1];  // [B,T,H]
    const float* Wx    = (const float*)d_in[2];  // [H,DI]
    const float* bias  = (const float*)d_in[3];  // [H]
    const float* Wh    = (const float*)d_in[4];  // [H,H]
    const float* Wy    = (const float*)d_in[5];  // [DO,H]
    const float* ah0   = (const float*)d_in[6];  // [H]

    float* out    = (float*)d_out;                  // [B,T,DO] first
    float* hstore = out + (size_t)B_ * T_ * DO_;    // [B,T,H] second

    const int xp_smem = (DI_ * H_ + DI_ * INS_STRIDE) * (int)sizeof(float);  // 67872 B
    static int attr_done = 0;
    if (!attr_done) {
        cudaFuncSetAttribute(xp_gemm_kernel,
                             cudaFuncAttributeMaxDynamicSharedMemorySize, xp_smem);
        cudaFuncSetAttribute(xp_gemm_kernel,
                             cudaFuncAttributePreferredSharedMemoryCarveout,
                             cudaSharedmemCarveoutMaxShared);
        attr_done = 1;
    }

    xp_gemm_kernel<<<1024, 256, xp_smem>>>(inp, Wx, bias);
    scan_kernel<<<B_ / 2, 128>>>(noise, Wh, ah0, hstore);
    outproj_kernel<<<(B_ * T_) / 256, 256>>>(hstore, Wy, out);
}